// round 9
// baseline (speedup 1.0000x reference)
#include <cuda_runtime.h>
#include <cuda_bf16.h>
#include <math.h>

#define IMG 224
#define HALF 112
#define OFF 56.0f
#define TL_BASE 38
#define TL_RANGE 18.0f
#define RPB 16           // output rows per block
#define THREADS 224
#define HCAP 10          // staged source-row capacity (max span for RPB=16, scale<=0.492)

__device__ __forceinline__ float mask1d(float v, float t, float l) {
    float z1 = 10.0f * (v - t + l);
    float z2 = 10.0f * (v - t - l);
    float s1 = 1.0f / (1.0f + __expf(-z1));
    float s2 = 1.0f / (1.0f + __expf(-z2));
    return s1 - s2;
}

__global__ __launch_bounds__(THREADS, 6)
void attention_crop_kernel(const float* __restrict__ apn,
                           const float* __restrict__ in,
                           float* __restrict__ out) {
    const int b   = blockIdx.y;
    const int tid = threadIdx.x;

    // Per-batch crop params (integer part first: needed for load addresses)
    const float a0p = __ldg(&apn[b * 3 + 0]);
    const float a1p = __ldg(&apn[b * 3 + 1]);
    const float a2p = __ldg(&apn[b * 3 + 2]);
    const int tx = HALF + (int)truncf(a0p * OFF + 0.5f);
    const int ty = HALF + (int)truncf(a1p * OFF + 0.5f);
    const int tl = TL_BASE + (int)truncf((a2p + 1.0f) * 0.5f * TL_RANGE);
    const int in_size = 2 * tl;
    const float scale = (float)in_size * (1.0f / 224.0f);
    const float txf = (float)tx, tyf = (float)ty, tlf = (float)tl;

    // Column source indices (cheap — compute before the expf-heavy weights)
    float srcc = fmaxf((tid + 0.5f) * scale - 0.5f, 0.0f);
    int   ci0  = (int)srcc;
    float wc   = srcc - (float)ci0;
    int   ci1  = min(ci0 + 1, in_size - 1);
    const int c0 = (ty - tl) + ci0;
    const int c1 = (ty - tl) + ci1;

    // Source-row window for this block (uniform across threads)
    const int rb = blockIdx.x * RPB;
    const int i_first = (int)fmaxf((rb + 0.5f) * scale - 0.5f, 0.0f);
    const int abs_first = (tx - tl) + i_first;
    const int i_last_lo = (int)fmaxf((rb + RPB - 1 + 0.5f) * scale - 0.5f, 0.0f);
    const int i_last    = min(i_last_lo + 1, in_size - 1);
    const int nrows     = i_last - i_first + 1;          // <= HCAP

    __shared__ int   s_q0[RPB];
    __shared__ int   s_q1[RPB];
    __shared__ float s_w0[RPB];
    __shared__ float s_w1[RPB];
    __shared__ __align__(16) float h[3 * HCAP * IMG];    // 26880 B

    if (tid < RPB) {
        const int r = rb + tid;
        float src = fmaxf((r + 0.5f) * scale - 0.5f, 0.0f);
        int   i0  = (int)src;
        float wr  = src - (float)i0;
        int   i1  = min(i0 + 1, in_size - 1);
        s_q0[tid] = i0 - i_first;
        s_q1[tid] = i1 - i_first;
        const float r0a = (float)((tx - tl) + i0);
        const float r1a = (float)((tx - tl) + i1);
        s_w0[tid] = (1.0f - wr) * mask1d(r0a, txf, tlf);
        s_w1[tid] = wr          * mask1d(r1a, txf, tlf);
    }

    const float* __restrict__ inb  = in  + (size_t)b * (3 * IMG * IMG);
    float*       __restrict__ outb = out + (size_t)b * (3 * IMG * IMG);

    // ---- Build: fixed-trip, predicated, so ptxas batches the LDGs (high MLP).
    // Loads are issued first; the expf-based column weights below overlap them.
    const float* p0 = inb + abs_first * IMG + c0;
    const float* p1 = inb + abs_first * IMG + c1;

    float v0[HCAP * 3], v1[HCAP * 3];
    #pragma unroll
    for (int q = 0; q < HCAP; q++) {
        if (q < nrows) {
            #pragma unroll
            for (int ch = 0; ch < 3; ch++) {
                v0[q * 3 + ch] = __ldg(p0 + ch * (IMG * IMG) + q * IMG);
                v1[q * 3 + ch] = __ldg(p1 + ch * (IMG * IMG) + q * IMG);
            }
        }
    }

    // Column weights (MUFU work overlaps the in-flight loads)
    const float a0c = (1.0f - wc) * mask1d((float)c0, tyf, tlf);
    const float a1c = wc          * mask1d((float)c1, tyf, tlf);

    #pragma unroll
    for (int q = 0; q < HCAP; q++) {
        if (q < nrows) {
            #pragma unroll
            for (int ch = 0; ch < 3; ch++) {
                h[(ch * HCAP + q) * IMG + tid] =
                    fmaf(a0c, v0[q * 3 + ch], a1c * v1[q * 3 + ch]);
            }
        }
    }
    __syncthreads();

    // ---- Consume: vertical combine, LDS.128 -> streaming STG.128 ----
    const int g  = tid % 56;        // column group: cols 4g..4g+3
    const int ry = tid / 56;        // 0..3
    float* ob = outb + rb * IMG + 4 * g;

    #pragma unroll
    for (int ch = 0; ch < 3; ch++) {
        #pragma unroll
        for (int k = 0; k < 4; k++) {
            const int   rr = k * 4 + ry;
            const int   q0 = s_q0[rr];
            const int   q1 = s_q1[rr];
            const float w0 = s_w0[rr];
            const float w1 = s_w1[rr];
            const float4 hv0 = *reinterpret_cast<const float4*>(&h[(ch * HCAP + q0) * IMG + 4 * g]);
            const float4 hv1 = *reinterpret_cast<const float4*>(&h[(ch * HCAP + q1) * IMG + 4 * g]);
            float4 o;
            o.x = fmaf(w0, hv0.x, w1 * hv1.x);
            o.y = fmaf(w0, hv0.y, w1 * hv1.y);
            o.z = fmaf(w0, hv0.z, w1 * hv1.z);
            o.w = fmaf(w0, hv0.w, w1 * hv1.w);
            __stcs(reinterpret_cast<float4*>(&ob[ch * (IMG * IMG) + rr * IMG]), o);
        }
    }
}

extern "C" void kernel_launch(void* const* d_in, const int* in_sizes, int n_in,
                              void* d_out, int out_size) {
    const float* apn = (const float*)d_in[0];   // [256, 3]
    const float* in  = (const float*)d_in[1];   // [256, 3, 224, 224]
    float* out = (float*)d_out;                 // [256, 3, 224, 224]

    dim3 grid(IMG / RPB, 256);                  // (14 row-chunks, B)
    attention_crop_kernel<<<grid, THREADS>>>(apn, in, out);
}

// round 12
// speedup vs baseline: 2.0840x; 2.0840x over previous
#include <cuda_runtime.h>
#include <cuda_bf16.h>
#include <math.h>

#define IMG 224
#define HALF 112
#define OFF 56.0f
#define TL_BASE 38
#define TL_RANGE 18.0f
#define RPB 16           // output rows per block
#define THREADS 224
#define HCAP 10          // staged source-row capacity (max span for RPB=16, scale<=0.4911)
#define CHS (IMG * IMG)  // channel stride

__device__ __forceinline__ float mask1d(float v, float t, float l) {
    float z1 = 10.0f * (v - t + l);
    float z2 = 10.0f * (v - t - l);
    float s1 = 1.0f / (1.0f + __expf(-z1));
    float s2 = 1.0f / (1.0f + __expf(-z2));
    return s1 - s2;
}

__global__ __launch_bounds__(THREADS, 8)
void attention_crop_kernel(const float* __restrict__ apn,
                           const float* __restrict__ in,
                           float* __restrict__ out) {
    const int b   = blockIdx.y;
    const int tid = threadIdx.x;

    // Per-batch crop params
    const float a0p = __ldg(&apn[b * 3 + 0]);
    const float a1p = __ldg(&apn[b * 3 + 1]);
    const float a2p = __ldg(&apn[b * 3 + 2]);
    const int tx = HALF + (int)truncf(a0p * OFF + 0.5f);
    const int ty = HALF + (int)truncf(a1p * OFF + 0.5f);
    const int tl = TL_BASE + (int)truncf((a2p + 1.0f) * 0.5f * TL_RANGE);
    const int in_size = 2 * tl;
    const float scale = (float)in_size * (1.0f / 224.0f);
    const float txf = (float)tx, tyf = (float)ty, tlf = (float)tl;

    // Column coefficients for col = tid (registers)
    float srcc = fmaxf((tid + 0.5f) * scale - 0.5f, 0.0f);
    int   ci0  = (int)srcc;
    float wc   = srcc - (float)ci0;
    int   ci1  = min(ci0 + 1, in_size - 1);
    const int   c0  = (ty - tl) + ci0;
    const int   c1  = (ty - tl) + ci1;
    const float a0c = (1.0f - wc) * mask1d((float)c0, tyf, tlf);
    const float a1c = wc          * mask1d((float)c1, tyf, tlf);

    // Source-row window for this block (uniform across threads)
    const int rb = blockIdx.x * RPB;
    const int i_first = (int)fmaxf((rb + 0.5f) * scale - 0.5f, 0.0f);
    const int abs_first = (tx - tl) + i_first;
    const int i_last_lo = (int)fmaxf((rb + RPB - 1 + 0.5f) * scale - 0.5f, 0.0f);
    const int i_last    = min(i_last_lo + 1, in_size - 1);
    const int nrows     = i_last - i_first + 1;          // <= HCAP

    __shared__ int   s_q0[RPB];
    __shared__ int   s_q1[RPB];
    __shared__ float s_w0[RPB];
    __shared__ float s_w1[RPB];
    __shared__ __align__(16) float h[3 * HCAP * IMG];    // 26880 B

    if (tid < RPB) {
        const int r = rb + tid;
        float src = fmaxf((r + 0.5f) * scale - 0.5f, 0.0f);
        int   i0  = (int)src;
        float wr  = src - (float)i0;
        int   i1  = min(i0 + 1, in_size - 1);
        s_q0[tid] = i0 - i_first;
        s_q1[tid] = i1 - i_first;
        const float r0a = (float)((tx - tl) + i0);
        const float r1a = (float)((tx - tl) + i1);
        s_w0[tid] = (1.0f - wr) * mask1d(r0a, txf, tlf);
        s_w1[tid] = wr          * mask1d(r1a, txf, tlf);
    }

    const float* __restrict__ inb  = in  + (size_t)b * (3 * CHS);
    float*       __restrict__ outb = out + (size_t)b * (3 * CHS);

    // ---- Build: 2 source rows per iteration -> 12 LDGs batched (MLP), 12 regs staging.
    {
        const float* p0 = inb + abs_first * IMG + c0;
        const float* p1 = inb + abs_first * IMG + c1;
        float* hp = h + tid;

        int q = 0;
        for (; q + 2 <= nrows; q += 2) {
            const int o0 = q * IMG;
            const int o1 = (q + 1) * IMG;
            // 12 independent loads (all issued before any use)
            const float x0a = __ldg(p0 + 0 * CHS + o0);
            const float x0b = __ldg(p1 + 0 * CHS + o0);
            const float x1a = __ldg(p0 + 1 * CHS + o0);
            const float x1b = __ldg(p1 + 1 * CHS + o0);
            const float x2a = __ldg(p0 + 2 * CHS + o0);
            const float x2b = __ldg(p1 + 2 * CHS + o0);
            const float y0a = __ldg(p0 + 0 * CHS + o1);
            const float y0b = __ldg(p1 + 0 * CHS + o1);
            const float y1a = __ldg(p0 + 1 * CHS + o1);
            const float y1b = __ldg(p1 + 1 * CHS + o1);
            const float y2a = __ldg(p0 + 2 * CHS + o1);
            const float y2b = __ldg(p1 + 2 * CHS + o1);

            hp[(0 * HCAP + q) * IMG]     = fmaf(a0c, x0a, a1c * x0b);
            hp[(1 * HCAP + q) * IMG]     = fmaf(a0c, x1a, a1c * x1b);
            hp[(2 * HCAP + q) * IMG]     = fmaf(a0c, x2a, a1c * x2b);
            hp[(0 * HCAP + q + 1) * IMG] = fmaf(a0c, y0a, a1c * y0b);
            hp[(1 * HCAP + q + 1) * IMG] = fmaf(a0c, y1a, a1c * y1b);
            hp[(2 * HCAP + q + 1) * IMG] = fmaf(a0c, y2a, a1c * y2b);
        }
        if (q < nrows) {                         // odd tail row
            const int o0 = q * IMG;
            const float x0a = __ldg(p0 + 0 * CHS + o0);
            const float x0b = __ldg(p1 + 0 * CHS + o0);
            const float x1a = __ldg(p0 + 1 * CHS + o0);
            const float x1b = __ldg(p1 + 1 * CHS + o0);
            const float x2a = __ldg(p0 + 2 * CHS + o0);
            const float x2b = __ldg(p1 + 2 * CHS + o0);
            hp[(0 * HCAP + q) * IMG] = fmaf(a0c, x0a, a1c * x0b);
            hp[(1 * HCAP + q) * IMG] = fmaf(a0c, x1a, a1c * x1b);
            hp[(2 * HCAP + q) * IMG] = fmaf(a0c, x2a, a1c * x2b);
        }
    }
    __syncthreads();

    // ---- Consume: vertical combine, LDS.128 -> STG.128 ----
    const int g  = tid % 56;        // column group: cols 4g..4g+3
    const int ry = tid / 56;        // 0..3
    float* ob = outb + rb * IMG + 4 * g;

    #pragma unroll
    for (int ch = 0; ch < 3; ch++) {
        #pragma unroll
        for (int k = 0; k < 4; k++) {
            const int   rr = k * 4 + ry;
            const int   q0 = s_q0[rr];
            const int   q1 = s_q1[rr];
            const float w0 = s_w0[rr];
            const float w1 = s_w1[rr];
            const float4 hv0 = *reinterpret_cast<const float4*>(&h[(ch * HCAP + q0) * IMG + 4 * g]);
            const float4 hv1 = *reinterpret_cast<const float4*>(&h[(ch * HCAP + q1) * IMG + 4 * g]);
            float4 o;
            o.x = fmaf(w0, hv0.x, w1 * hv1.x);
            o.y = fmaf(w0, hv0.y, w1 * hv1.y);
            o.z = fmaf(w0, hv0.z, w1 * hv1.z);
            o.w = fmaf(w0, hv0.w, w1 * hv1.w);
            *reinterpret_cast<float4*>(&ob[ch * CHS + rr * IMG]) = o;
        }
    }
}

extern "C" void kernel_launch(void* const* d_in, const int* in_sizes, int n_in,
                              void* d_out, int out_size) {
    const float* apn = (const float*)d_in[0];   // [256, 3]
    const float* in  = (const float*)d_in[1];   // [256, 3, 224, 224]
    float* out = (float*)d_out;                 // [256, 3, 224, 224]

    dim3 grid(IMG / RPB, 256);                  // (14 row-chunks, B)
    attention_crop_kernel<<<grid, THREADS>>>(apn, in, out);
}

// round 13
// speedup vs baseline: 2.1366x; 1.0252x over previous
#include <cuda_runtime.h>
#include <cuda_bf16.h>
#include <math.h>

#define IMG 224
#define HALF 112
#define OFF 56.0f
#define TL_BASE 38
#define TL_RANGE 18.0f
#define RPB 16           // output rows per block
#define THREADS 224
#define HCAP 10          // staged source-row capacity (max span for RPB=16, scale<=0.4911)
#define CHS (IMG * IMG)  // channel stride

__device__ __forceinline__ float mask1d(float v, float t, float l) {
    float z1 = 10.0f * (v - t + l);
    float z2 = 10.0f * (v - t - l);
    float s1 = 1.0f / (1.0f + __expf(-z1));
    float s2 = 1.0f / (1.0f + __expf(-z2));
    return s1 - s2;
}

__global__ __launch_bounds__(THREADS)
void attention_crop_kernel(const float* __restrict__ apn,
                           const float* __restrict__ in,
                           float* __restrict__ out) {
    const int b   = blockIdx.y;
    const int tid = threadIdx.x;

    // Per-batch crop params
    const float a0p = __ldg(&apn[b * 3 + 0]);
    const float a1p = __ldg(&apn[b * 3 + 1]);
    const float a2p = __ldg(&apn[b * 3 + 2]);
    const int tx = HALF + (int)truncf(a0p * OFF + 0.5f);
    const int ty = HALF + (int)truncf(a1p * OFF + 0.5f);
    const int tl = TL_BASE + (int)truncf((a2p + 1.0f) * 0.5f * TL_RANGE);
    const int in_size = 2 * tl;
    const float scale = (float)in_size * (1.0f / 224.0f);
    const float txf = (float)tx, tyf = (float)ty, tlf = (float)tl;

    // Column coefficients for col = tid (registers)
    float srcc = fmaxf((tid + 0.5f) * scale - 0.5f, 0.0f);
    int   ci0  = (int)srcc;
    float wc   = srcc - (float)ci0;
    int   ci1  = min(ci0 + 1, in_size - 1);
    const int   c0  = (ty - tl) + ci0;
    const int   c1  = (ty - tl) + ci1;
    const float a0c = (1.0f - wc) * mask1d((float)c0, tyf, tlf);
    const float a1c = wc          * mask1d((float)c1, tyf, tlf);

    // Source-row window for this block (uniform across threads)
    const int rb = blockIdx.x * RPB;
    const int i_first = (int)fmaxf((rb + 0.5f) * scale - 0.5f, 0.0f);
    const int abs_first = (tx - tl) + i_first;
    const int i_last_lo = (int)fmaxf((rb + RPB - 1 + 0.5f) * scale - 0.5f, 0.0f);
    const int i_last    = min(i_last_lo + 1, in_size - 1);
    const int nrows     = i_last - i_first + 1;          // <= HCAP

    // Packed per-row table: (q0 bits, q1 bits, w0, w1) — one LDS.128 broadcast
    __shared__ __align__(16) float4 s_tab[RPB];
    __shared__ __align__(16) float  h[3 * HCAP * IMG];   // 26880 B

    if (tid < RPB) {
        const int r = rb + tid;
        float src = fmaxf((r + 0.5f) * scale - 0.5f, 0.0f);
        int   i0  = (int)src;
        float wr  = src - (float)i0;
        int   i1  = min(i0 + 1, in_size - 1);
        const float r0a = (float)((tx - tl) + i0);
        const float r1a = (float)((tx - tl) + i1);
        s_tab[tid] = make_float4(__int_as_float(i0 - i_first),
                                 __int_as_float(i1 - i_first),
                                 (1.0f - wr) * mask1d(r0a, txf, tlf),
                                 wr          * mask1d(r1a, txf, tlf));
    }

    const float* __restrict__ inb  = in  + (size_t)b * (3 * CHS);
    float*       __restrict__ outb = out + (size_t)b * (3 * CHS);

    // ---- Build: 2 source rows per iteration -> 12 LDGs batched ----
    {
        const float* p0 = inb + abs_first * IMG + c0;
        const float* p1 = inb + abs_first * IMG + c1;
        float* hp = h + tid;

        int q = 0;
        for (; q + 2 <= nrows; q += 2) {
            const int o0 = q * IMG;
            const int o1 = (q + 1) * IMG;
            const float x0a = __ldg(p0 + 0 * CHS + o0);
            const float x0b = __ldg(p1 + 0 * CHS + o0);
            const float x1a = __ldg(p0 + 1 * CHS + o0);
            const float x1b = __ldg(p1 + 1 * CHS + o0);
            const float x2a = __ldg(p0 + 2 * CHS + o0);
            const float x2b = __ldg(p1 + 2 * CHS + o0);
            const float y0a = __ldg(p0 + 0 * CHS + o1);
            const float y0b = __ldg(p1 + 0 * CHS + o1);
            const float y1a = __ldg(p0 + 1 * CHS + o1);
            const float y1b = __ldg(p1 + 1 * CHS + o1);
            const float y2a = __ldg(p0 + 2 * CHS + o1);
            const float y2b = __ldg(p1 + 2 * CHS + o1);

            hp[(0 * HCAP + q) * IMG]     = fmaf(a0c, x0a, a1c * x0b);
            hp[(1 * HCAP + q) * IMG]     = fmaf(a0c, x1a, a1c * x1b);
            hp[(2 * HCAP + q) * IMG]     = fmaf(a0c, x2a, a1c * x2b);
            hp[(0 * HCAP + q + 1) * IMG] = fmaf(a0c, y0a, a1c * y0b);
            hp[(1 * HCAP + q + 1) * IMG] = fmaf(a0c, y1a, a1c * y1b);
            hp[(2 * HCAP + q + 1) * IMG] = fmaf(a0c, y2a, a1c * y2b);
        }
        if (q < nrows) {
            const int o0 = q * IMG;
            const float x0a = __ldg(p0 + 0 * CHS + o0);
            const float x0b = __ldg(p1 + 0 * CHS + o0);
            const float x1a = __ldg(p0 + 1 * CHS + o0);
            const float x1b = __ldg(p1 + 1 * CHS + o0);
            const float x2a = __ldg(p0 + 2 * CHS + o0);
            const float x2b = __ldg(p1 + 2 * CHS + o0);
            hp[(0 * HCAP + q) * IMG] = fmaf(a0c, x0a, a1c * x0b);
            hp[(1 * HCAP + q) * IMG] = fmaf(a0c, x1a, a1c * x1b);
            hp[(2 * HCAP + q) * IMG] = fmaf(a0c, x2a, a1c * x2b);
        }
    }
    __syncthreads();

    // ---- Consume: 4 CONSECUTIVE rows per thread, rolling h-row cache ----
    const int g  = tid % 56;        // column group: cols 4g..4g+3
    const int ry = tid / 56;        // 0..3 -> rows 4ry..4ry+3
    float* ob = outb + (rb + 4 * ry) * IMG + 4 * g;

    #pragma unroll
    for (int ch = 0; ch < 3; ch++) {
        const float* hc = h + ch * (HCAP * IMG) + 4 * g;
        float* oc = ob + ch * CHS;

        // Row 0 of this thread's strip
        float4 t = s_tab[4 * ry];
        int cur0 = __float_as_int(t.x);
        int cur1 = __float_as_int(t.y);
        float4 hv0 = *reinterpret_cast<const float4*>(hc + cur0 * IMG);
        float4 hv1 = (cur1 == cur0) ? hv0
                   : *reinterpret_cast<const float4*>(hc + cur1 * IMG);
        float4 o;
        o.x = fmaf(t.z, hv0.x, t.w * hv1.x);
        o.y = fmaf(t.z, hv0.y, t.w * hv1.y);
        o.z = fmaf(t.z, hv0.z, t.w * hv1.z);
        o.w = fmaf(t.z, hv0.w, t.w * hv1.w);
        *reinterpret_cast<float4*>(oc) = o;

        // Rows 1..3: roll the cache (all conditions block-uniform)
        #pragma unroll
        for (int j = 1; j < 4; j++) {
            t = s_tab[4 * ry + j];
            const int a0 = __float_as_int(t.x);
            const int a1 = __float_as_int(t.y);
            if (a0 != cur0) {
                hv0 = (a0 == cur1) ? hv1
                    : *reinterpret_cast<const float4*>(hc + a0 * IMG);
                cur0 = a0;
            }
            if (a1 != cur1) {
                hv1 = (a1 == a0) ? hv0
                    : *reinterpret_cast<const float4*>(hc + a1 * IMG);
                cur1 = a1;
            }
            o.x = fmaf(t.z, hv0.x, t.w * hv1.x);
            o.y = fmaf(t.z, hv0.y, t.w * hv1.y);
            o.z = fmaf(t.z, hv0.z, t.w * hv1.z);
            o.w = fmaf(t.z, hv0.w, t.w * hv1.w);
            *reinterpret_cast<float4*>(oc + j * IMG) = o;
        }
    }
}

extern "C" void kernel_launch(void* const* d_in, const int* in_sizes, int n_in,
                              void* d_out, int out_size) {
    const float* apn = (const float*)d_in[0];   // [256, 3]
    const float* in  = (const float*)d_in[1];   // [256, 3, 224, 224]
    float* out = (float*)d_out;                 // [256, 3, 224, 224]

    dim3 grid(IMG / RPB, 256);                  // (14 row-chunks, B)
    attention_crop_kernel<<<grid, THREADS>>>(apn, in, out);
}

// round 14
// speedup vs baseline: 2.1414x; 1.0022x over previous
#include <cuda_runtime.h>
#include <cuda_bf16.h>
#include <math.h>

#define IMG 224
#define HALF 112
#define OFF 56.0f
#define TL_BASE 38
#define TL_RANGE 18.0f
#define RPB 16           // output rows per block
#define THREADS 224      // one thread per output column
#define CHS (IMG * IMG)  // channel stride

__device__ __forceinline__ float mask1d(float v, float t, float l) {
    float z1 = 10.0f * (v - t + l);
    float z2 = 10.0f * (v - t - l);
    float s1 = 1.0f / (1.0f + __expf(-z1));
    float s2 = 1.0f / (1.0f + __expf(-z2));
    return s1 - s2;
}

__global__ __launch_bounds__(THREADS, 8)
void attention_crop_kernel(const float* __restrict__ apn,
                           const float* __restrict__ in,
                           float* __restrict__ out) {
    const int b   = blockIdx.y;
    const int tid = threadIdx.x;

    // Per-batch crop params
    const float a0p = __ldg(&apn[b * 3 + 0]);
    const float a1p = __ldg(&apn[b * 3 + 1]);
    const float a2p = __ldg(&apn[b * 3 + 2]);
    const int tx = HALF + (int)truncf(a0p * OFF + 0.5f);
    const int ty = HALF + (int)truncf(a1p * OFF + 0.5f);
    const int tl = TL_BASE + (int)truncf((a2p + 1.0f) * 0.5f * TL_RANGE);
    const int in_size = 2 * tl;
    const float scale = (float)in_size * (1.0f / 224.0f);
    const float txf = (float)tx, tyf = (float)ty, tlf = (float)tl;

    // Column coefficients for col = tid (registers)
    float srcc = fmaxf((tid + 0.5f) * scale - 0.5f, 0.0f);
    int   ci0  = (int)srcc;
    float wc   = srcc - (float)ci0;
    int   ci1  = min(ci0 + 1, in_size - 1);
    const int   c0  = (ty - tl) + ci0;
    const int   c1  = (ty - tl) + ci1;
    const float a0c = (1.0f - wc) * mask1d((float)c0, tyf, tlf);
    const float a1c = wc          * mask1d((float)c1, tyf, tlf);

    // Source-row window for this block (uniform across threads)
    const int rb = blockIdx.x * RPB;
    const int i_first = (int)fmaxf((rb + 0.5f) * scale - 0.5f, 0.0f);
    const int abs_first = (tx - tl) + i_first;
    const int i_last_lo = (int)fmaxf((rb + RPB - 1 + 0.5f) * scale - 0.5f, 0.0f);
    const int i_last    = min(i_last_lo + 1, in_size - 1);
    const int nrows     = i_last - i_first + 1;

    // Packed per-row table: (q0 bits, q1 bits, w0, w1) — one LDS.128 broadcast/row
    __shared__ __align__(16) float4 s_tab[RPB];
    if (tid < RPB) {
        const int r = rb + tid;
        float src = fmaxf((r + 0.5f) * scale - 0.5f, 0.0f);
        int   i0  = (int)src;
        float wr  = src - (float)i0;
        int   i1  = min(i0 + 1, in_size - 1);
        const float r0a = (float)((tx - tl) + i0);
        const float r1a = (float)((tx - tl) + i1);
        s_tab[tid] = make_float4(__int_as_float(i0 - i_first),
                                 __int_as_float(i1 - i_first),
                                 (1.0f - wr) * mask1d(r0a, txf, tlf),
                                 wr          * mask1d(r1a, txf, tlf));
    }
    __syncthreads();

    const float* __restrict__ inb  = in  + (size_t)b * (3 * CHS);
    float*       __restrict__ outb = out + (size_t)b * (3 * CHS);

    const float* p0 = inb + abs_first * IMG + c0;
    const float* p1 = inb + abs_first * IMG + c1;
    float*       ob = outb + rb * IMG + tid;

    // Triple-buffered register roll over source rows; 3 channels in parallel
    // (6 batched LDGs per new source row). All control flow is block-uniform.
    float va[3], vb[3], vc[3];
    #pragma unroll
    for (int ch = 0; ch < 3; ch++)
        va[ch] = fmaf(a0c, __ldg(p0 + ch * CHS), a1c * __ldg(p1 + ch * CHS));
    if (nrows > 1) {
        #pragma unroll
        for (int ch = 0; ch < 3; ch++)
            vb[ch] = fmaf(a0c, __ldg(p0 + ch * CHS + IMG), a1c * __ldg(p1 + ch * CHS + IMG));
    } else {
        #pragma unroll
        for (int ch = 0; ch < 3; ch++) vb[ch] = va[ch];
    }
    if (nrows > 2) {
        #pragma unroll
        for (int ch = 0; ch < 3; ch++)
            vc[ch] = fmaf(a0c, __ldg(p0 + ch * CHS + 2 * IMG), a1c * __ldg(p1 + ch * CHS + 2 * IMG));
    } else {
        #pragma unroll
        for (int ch = 0; ch < 3; ch++) vc[ch] = vb[ch];
    }

    int q = 0;
    #pragma unroll
    for (int r = 0; r < RPB; r++) {
        const float4 t  = s_tab[r];
        const int    q0 = __float_as_int(t.x);
        const int    q1 = __float_as_int(t.y);

        if (q0 != q) {                       // advance exactly one source row
            #pragma unroll
            for (int ch = 0; ch < 3; ch++) { va[ch] = vb[ch]; vb[ch] = vc[ch]; }
            if (q0 + 2 < nrows) {            // prefetch one row ahead
                const int o = (q0 + 2) * IMG;
                #pragma unroll
                for (int ch = 0; ch < 3; ch++)
                    vc[ch] = fmaf(a0c, __ldg(p0 + ch * CHS + o),
                                  a1c * __ldg(p1 + ch * CHS + o));
            }
            q = q0;
        }

        const bool two = (q1 != q0);         // uniform; false only at clamp edge
        #pragma unroll
        for (int ch = 0; ch < 3; ch++) {
            const float v1 = two ? vb[ch] : va[ch];
            ob[ch * CHS + r * IMG] = fmaf(t.z, va[ch], t.w * v1);
        }
    }
}

extern "C" void kernel_launch(void* const* d_in, const int* in_sizes, int n_in,
                              void* d_out, int out_size) {
    const float* apn = (const float*)d_in[0];   // [256, 3]
    const float* in  = (const float*)d_in[1];   // [256, 3, 224, 224]
    float* out = (float*)d_out;                 // [256, 3, 224, 224]

    dim3 grid(IMG / RPB, 256);                  // (14 row-chunks, B)
    attention_crop_kernel<<<grid, THREADS>>>(apn, in, out);
}